// round 14
// baseline (speedup 1.0000x reference)
#include <cuda_runtime.h>
#include <cuda_fp16.h>
#include <cstdint>

// ---------------------------------------------------------------------------
// SelfAttention: out = softmax((xWq+bq)(xWk+bk)^T / 32) (xWv+bv)
// B=4, N=2048, D=1024, fp32 in/out.  fp16 mma.sync m16n8k16 (fp32 accum).
// ldmatrix.m8n8.x4 fragment loads; 128-thread CTAs, 64x64 warp tiles.
// Softmax fused away (unnormalized exp + distributed rowsums).
// SINGLE PERSISTENT KERNEL: 296 CTAs pull QKV/scores/PV tiles from a global
// queue; dependencies enforced with device counters (threadfence + atomics).
// Queue order QKV -> scores -> PV makes the dependency DAG acyclic in pull
// order => no deadlock; phase tails overlap across phases.
// ---------------------------------------------------------------------------

static constexpr int  BATCH = 4;
static constexpr int  SEQ   = 2048;
static constexpr int  DIM   = 1024;
static constexpr long MROWS = (long)BATCH * SEQ;   // 8192
static constexpr int  NCTA_N = SEQ / 128;          // 16 score col-tiles per row

static constexpr int NQKV = 24 * 64;               // 1536
static constexpr int NSC  = 16 * 16 * BATCH;       // 1024
static constexpr int NPV  = 8 * 16 * BATCH;        // 512
static constexpr int NTOT = NQKV + NSC + NPV;      // 3072

// Scratch (__device__ globals: allocation-free rule)
__device__ __half g_x[MROWS * DIM];
__device__ __half g_w[(long)3 * DIM * DIM];        // W^T concat [3072][1024]
__device__ __half g_q[MROWS * DIM];
__device__ __half g_k[MROWS * DIM];
__device__ __half g_vt[(long)BATCH * DIM * SEQ];   // V^T per batch [dim][token]
__device__ __half g_p[(long)BATCH * SEQ * SEQ];    // unnormalized exp, fp16
__device__ float  g_rs[MROWS * NCTA_N];            // per-row partial sums
__device__ float  g_b[3 * DIM];

// scheduling state (zeroed by prep each invocation)
__device__ int g_head;
__device__ int g_qdone[64];
__device__ int g_kdone[64];
__device__ int g_pdone[64];
__device__ int g_vdone[BATCH];

// ---------------- helpers ----------------
__device__ __forceinline__ int swz(int r) {        // smem chunk swizzle
    return ((r & 3) << 1) | ((r >> 2) & 1);
}
__device__ __forceinline__ uint32_t smem_u32(const void* p) {
    uint32_t a;
    asm("{ .reg .u64 t; cvta.to.shared.u64 t, %1; cvt.u32.u64 %0, t; }" : "=r"(a) : "l"(p));
    return a;
}
__device__ __forceinline__ void cp16(uint32_t dst, const void* src) {
    asm volatile("cp.async.cg.shared.global [%0], [%1], 16;" :: "r"(dst), "l"(src));
}
__device__ __forceinline__ void cp_commit() { asm volatile("cp.async.commit_group;" ::: "memory"); }
template <int N>
__device__ __forceinline__ void cp_wait() { asm volatile("cp.async.wait_group %0;" :: "n"(N) : "memory"); }

__device__ __forceinline__ void ldsm4(uint32_t& r0, uint32_t& r1,
                                      uint32_t& r2, uint32_t& r3, uint32_t addr) {
    asm volatile("ldmatrix.sync.aligned.m8n8.x4.shared.b16 {%0,%1,%2,%3}, [%4];"
                 : "=r"(r0), "=r"(r1), "=r"(r2), "=r"(r3) : "r"(addr));
}

__device__ __forceinline__ void mma_f16(float c[4],
                                        uint32_t a0, uint32_t a1, uint32_t a2, uint32_t a3,
                                        uint32_t b0, uint32_t b1) {
    asm volatile(
        "mma.sync.aligned.m16n8k16.row.col.f32.f16.f16.f32 "
        "{%0,%1,%2,%3}, {%4,%5,%6,%7}, {%8,%9}, {%0,%1,%2,%3};"
        : "+f"(c[0]), "+f"(c[1]), "+f"(c[2]), "+f"(c[3])
        : "r"(a0), "r"(a1), "r"(a2), "r"(a3), "r"(b0), "r"(b1));
}

__device__ __forceinline__ void spin_until(int* ctr, int need) {
    while (atomicAdd(ctr, 0) < need) __nanosleep(64);
}

// ---------------------------------------------------------------------------
static constexpr int STAGES  = 3;
static constexpr int TILE_B  = 128 * 64 * 2;       // 16 KB per operand tile
static constexpr int STAGE_B = 2 * TILE_B;         // 32 KB
static constexpr int SMEM_GB = STAGES * STAGE_B;   // 98304 B
static constexpr int NCTA_PERSIST = 296;           // 2 per SM x 148 SMs

// item decode: mode 1 = QKV, 2 = scores, 0 = PV
__device__ __forceinline__ void decode_item(int it, int& mode,
                                            int& bx, int& by, int& bz) {
    if (it < NQKV)            { mode = 1; bx = it % 24; by = it / 24; bz = 0; }
    else if (it < NQKV + NSC) { int t = it - NQKV;
                                mode = 2; bz = t >> 8; by = (t >> 4) & 15; bx = t & 15; }
    else                      { int t = it - NQKV - NSC;
                                mode = 0; bz = t >> 7; by = (t >> 3) & 15; bx = t & 7; }
}

__global__ void __launch_bounds__(128, 2) mega_kernel(
    const __half* __restrict__ xh, const __half* __restrict__ wh,
    const float* __restrict__ bb,
    __half* __restrict__ qh, __half* __restrict__ kh, __half* __restrict__ vt,
    __half* __restrict__ ph, float* __restrict__ rs, float* __restrict__ outp)
{
    extern __shared__ uint32_t sm[];
    __shared__ int s_item;

    const int tid  = threadIdx.x;
    const int warp = tid >> 5, lane = tid & 31;
    const int g = lane >> 2, tg = lane & 3;
    const int wm = warp >> 1, wn = warp & 1;        // 2x2 warps, 64x64 tiles
    const uint32_t sbase = smem_u32(sm);

    // ldmatrix per-lane geometry (frag rows satisfy row&7 == lane&7)
    const int sw    = swz(lane & 7);
    const int aRow  = (lane & 7) | (lane & 8);
    const int aCbit = lane >> 4;
    const int bRow  = (lane & 7) | ((lane >> 1) & 8);
    const int bCbit = (lane >> 3) & 1;

    for (;;) {
        __syncthreads();                            // protect s_item reuse
        if (tid == 0) s_item = atomicAdd(&g_head, 1);
        __syncthreads();
        const int it = s_item;
        if (it >= NTOT) return;

        int mode, bx, by, bz;
        decode_item(it, mode, bx, by, bz);

        // ---- dependency wait (queue order makes this deadlock-free) ----
        if (tid == 0) {
            if (mode == 2) {
                spin_until(&g_qdone[bz * 16 + by], 8);
                spin_until(&g_kdone[bz * 16 + bx], 8);
            } else if (mode == 0) {
                spin_until(&g_pdone[bz * 16 + by], 16);
                spin_until(&g_vdone[bz], 128);
            }
        }
        __syncthreads();
        __threadfence();                            // order: flag -> data reads

        // ---- per-tile operand setup ----
        const __half* A; const __half* B; int K, ldb;
        if (mode == 1)      { A = xh;  B = wh; K = DIM; ldb = DIM; }
        else if (mode == 2) { A = qh + (long)bz * SEQ * DIM;
                              B = kh + (long)bz * SEQ * DIM; K = DIM; ldb = DIM; }
        else                { A = ph + (long)bz * SEQ * SEQ;
                              B = vt + (long)bz * DIM * SEQ; K = SEQ; ldb = SEQ; }
        const int m0 = by * 128, n0 = bx * 128;
        const __half* Ag = A + (long)m0 * K;
        const __half* Bg = B + (long)n0 * ldb;

        auto load_stage = [&](int kt, int s) {
            const uint32_t as_ = sbase + (uint32_t)(s * STAGE_B);
            const uint32_t bs_ = as_ + TILE_B;
            #pragma unroll
            for (int i = 0; i < 8; i++) {
                int lin = tid + i * 128;
                int r = lin >> 3, c = lin & 7;
                uint32_t off = (uint32_t)(r * 128 + ((c ^ swz(r)) << 4));
                cp16(as_ + off, Ag + (long)r * K + kt * 64 + c * 8);
            }
            #pragma unroll
            for (int i = 0; i < 8; i++) {
                int lin = tid + i * 128;
                int r = lin >> 3, c = lin & 7;
                uint32_t off = (uint32_t)(r * 128 + ((c ^ swz(r)) << 4));
                cp16(bs_ + off, Bg + (long)r * ldb + kt * 64 + c * 8);
            }
        };

        float acc[4][8][4];
        #pragma unroll
        for (int i = 0; i < 4; i++)
            #pragma unroll
            for (int j = 0; j < 8; j++)
                #pragma unroll
                for (int l = 0; l < 4; l++) acc[i][j][l] = 0.f;

        const int nk = K / 64;
        #pragma unroll
        for (int s = 0; s < STAGES - 1; s++) { load_stage(s, s); cp_commit(); }

        int scur = 0;
        for (int kt = 0; kt < nk; kt++) {
            cp_wait<STAGES - 2>();
            __syncthreads();

            int pf = kt + STAGES - 1;
            if (pf < nk) {
                int sp = scur + (STAGES - 1); if (sp >= STAGES) sp -= STAGES;
                load_stage(pf, sp);
            }
            cp_commit();

            const uint32_t asb = sbase + (uint32_t)(scur * STAGE_B);
            const uint32_t aB0 = asb + (uint32_t)((wm * 64 + aRow) * 128);
            const uint32_t bB  = asb + TILE_B + (uint32_t)((wn * 64 + bRow) * 128);

            #pragma unroll
            for (int kkb = 0; kkb < 4; kkb++) {
                const uint32_t aco = (uint32_t)(((2 * kkb + aCbit) ^ sw) << 4);
                const uint32_t bco = (uint32_t)(((2 * kkb + bCbit) ^ sw) << 4);

                uint32_t af[4][4];
                #pragma unroll
                for (int mt = 0; mt < 4; mt++)
                    ldsm4(af[mt][0], af[mt][1], af[mt][2], af[mt][3],
                          aB0 + (uint32_t)(mt * 16 * 128) + aco);

                uint32_t bf[16];
                #pragma unroll
                for (int p = 0; p < 4; p++)
                    ldsm4(bf[4 * p], bf[4 * p + 1], bf[4 * p + 2], bf[4 * p + 3],
                          bB + (uint32_t)(p * 2048) + bco);

                #pragma unroll
                for (int mt = 0; mt < 4; mt++)
                    #pragma unroll
                    for (int nt = 0; nt < 8; nt++) {
                        int bi = ((nt >> 1) << 2) | ((nt & 1) << 1);
                        mma_f16(acc[mt][nt],
                                af[mt][0], af[mt][1], af[mt][2], af[mt][3],
                                bf[bi], bf[bi + 1]);
                    }
            }
            if (++scur == STAGES) scur = 0;
        }

        // ---- epilogues ----
        if (mode == 2) {
            __syncthreads();                        // reuse stage smem
            float* rsm = (float*)sm;                // [128 rows][2 halves]
            const float SC = 0.03125f;
            #pragma unroll
            for (int mt = 0; mt < 4; mt++) {
                int rr = wm * 64 + mt * 16 + g;
                int r0 = m0 + rr;
                float s0 = 0.f, s1 = 0.f;
                #pragma unroll
                for (int nt = 0; nt < 8; nt++) {
                    int cc = n0 + wn * 64 + nt * 8 + tg * 2;
                    __half2 h0 = __floats2half2_rn(__expf(acc[mt][nt][0] * SC),
                                                   __expf(acc[mt][nt][1] * SC));
                    __half2 h1 = __floats2half2_rn(__expf(acc[mt][nt][2] * SC),
                                                   __expf(acc[mt][nt][3] * SC));
                    long prow = (long)bz * SEQ;
                    *(__half2*)(ph + (prow + r0) * SEQ + cc)     = h0;
                    *(__half2*)(ph + (prow + r0 + 8) * SEQ + cc) = h1;
                    s0 += __half2float(h0.x) + __half2float(h0.y);
                    s1 += __half2float(h1.x) + __half2float(h1.y);
                }
                #pragma unroll
                for (int o = 1; o < 4; o <<= 1) {
                    s0 += __shfl_xor_sync(0xffffffffu, s0, o);
                    s1 += __shfl_xor_sync(0xffffffffu, s1, o);
                }
                if (tg == 0) {
                    rsm[(rr)     * 2 + wn] = s0;
                    rsm[(rr + 8) * 2 + wn] = s1;
                }
            }
            __syncthreads();
            if (tid < 128) {
                float sum = rsm[tid * 2] + rsm[tid * 2 + 1];
                rs[((long)bz * SEQ + m0 + tid) * NCTA_N + bx] = sum;
            }
            __threadfence();
            __syncthreads();
            if (tid == 0) atomicAdd(&g_pdone[bz * 16 + by], 1);
        } else if (mode == 1) {
            #pragma unroll
            for (int mt = 0; mt < 4; mt++) {
                int r0 = m0 + wm * 64 + mt * 16 + g;
                #pragma unroll
                for (int nt = 0; nt < 8; nt++) {
                    int cc = n0 + wn * 64 + nt * 8 + tg * 2;
                    float b0 = bb[cc], b1 = bb[cc + 1];
                    float v0 = acc[mt][nt][0] + b0, v1 = acc[mt][nt][1] + b1;
                    float v2 = acc[mt][nt][2] + b0, v3 = acc[mt][nt][3] + b1;
                    int buf = cc >> 10, loc = cc & 1023;
                    if (buf < 2) {
                        __half* dst = buf ? kh : qh;
                        *(__half2*)(dst + (long)r0 * DIM + loc) =
                            __floats2half2_rn(v0, v1);
                        *(__half2*)(dst + (long)(r0 + 8) * DIM + loc) =
                            __floats2half2_rn(v2, v3);
                    } else {                         // V -> Vt[dim][token]
                        int b_ = r0 >> 11, t = r0 & 2047;
                        long base0 = ((long)b_ * DIM + loc) * SEQ;
                        long base1 = base0 + SEQ;
                        vt[base0 + t]     = __float2half_rn(v0);
                        vt[base1 + t]     = __float2half_rn(v1);
                        vt[base0 + t + 8] = __float2half_rn(v2);
                        vt[base1 + t + 8] = __float2half_rn(v3);
                    }
                }
            }
            __threadfence();
            __syncthreads();
            if (tid == 0) {
                if (bx < 8)       atomicAdd(&g_qdone[by], 1);
                else if (bx < 16) atomicAdd(&g_kdone[by], 1);
                else              atomicAdd(&g_vdone[by >> 4], 1);
            }
        } else {                                    // mode 0: PV
            float* Cf = outp + (long)bz * SEQ * DIM;
            #pragma unroll
            for (int mt = 0; mt < 4; mt++) {
                int r0 = m0 + wm * 64 + mt * 16 + g;
                const float4* rs0 = (const float4*)(rs +
                    ((long)bz * SEQ + r0) * NCTA_N) + tg;
                const float4* rs1 = (const float4*)(rs +
                    ((long)bz * SEQ + r0 + 8) * NCTA_N) + tg;
                float4 a4 = *rs0, b4 = *rs1;
                float t0 = a4.x + a4.y + a4.z + a4.w;
                float t1 = b4.x + b4.y + b4.z + b4.w;
                #pragma unroll
                for (int o = 1; o < 4; o <<= 1) {
                    t0 += __shfl_xor_sync(0xffffffffu, t0, o);
                    t1 += __shfl_xor_sync(0xffffffffu, t1, o);
                }
                float inv0 = 1.f / t0, inv1 = 1.f / t1;
                #pragma unroll
                for (int nt = 0; nt < 8; nt++) {
                    int cc = n0 + wn * 64 + nt * 8 + tg * 2;
                    *(float2*)(Cf + (long)r0 * DIM + cc) =
                        make_float2(acc[mt][nt][0] * inv0, acc[mt][nt][1] * inv0);
                    *(float2*)(Cf + (long)(r0 + 8) * DIM + cc) =
                        make_float2(acc[mt][nt][2] * inv1, acc[mt][nt][3] * inv1);
                }
            }
        }
    }
}

// ---------------------------------------------------------------------------
// merged prep: x -> fp16, bias concat, W transposes, counter zeroing
// ---------------------------------------------------------------------------
static constexpr int NB_X = (int)(MROWS * DIM / 4 / 256);   // 8192 blocks
static constexpr int NB_W = 3 * (DIM / 32) * (DIM / 32);    // 3072 blocks

__global__ void __launch_bounds__(256) prep_all_kernel(
    const float* __restrict__ in, __half* __restrict__ out,
    const float* __restrict__ b0, const float* __restrict__ b1,
    const float* __restrict__ b2, float* __restrict__ bcat,
    const float* __restrict__ W0, const float* __restrict__ W1,
    const float* __restrict__ W2, __half* __restrict__ wout)
{
    const int bx = blockIdx.x;
    if (bx < NB_X) {
        int i = bx * 256 + threadIdx.x;
        float4 v = ((const float4*)in)[i];
        ((__half2*)out)[2 * i]     = __floats2half2_rn(v.x, v.y);
        ((__half2*)out)[2 * i + 1] = __floats2half2_rn(v.z, v.w);
    } else if (bx < NB_X + 12) {
        int i = (bx - NB_X) * 256 + threadIdx.x;
        if (i < DIM)          bcat[i] = b0[i];
        else if (i < 2 * DIM) bcat[i] = b1[i - DIM];
        else                  bcat[i] = b2[i - 2 * DIM];
    } else if (bx < NB_X + 12 + NB_W) {
        __shared__ float t[32][33];
        int widx = bx - NB_X - 12;
        int z    = widx >> 10;
        int rem  = widx & 1023;
        int r0 = (rem >> 5) * 32, c0 = (rem & 31) * 32;
        const float* W = z == 0 ? W0 : (z == 1 ? W1 : W2);
        __half* dst = wout + (long)z * DIM * DIM;
        int tx = threadIdx.x & 31, ty = threadIdx.x >> 5;
        #pragma unroll
        for (int j = 0; j < 4; j++)
            t[ty + j * 8][tx] = W[(long)(r0 + ty + j * 8) * DIM + c0 + tx];
        __syncthreads();
        #pragma unroll
        for (int j = 0; j < 4; j++) {
            float v = t[tx][ty + j * 8];
            dst[(long)(c0 + ty + j * 8) * DIM + r0 + tx] = __float2half_rn(v);
        }
    } else {                                        // zero scheduling state
        int i = threadIdx.x;
        if (i == 0) g_head = 0;
        if (i < 64) { g_qdone[i] = 0; g_kdone[i] = 0; g_pdone[i] = 0; }
        if (i < BATCH) g_vdone[i] = 0;
    }
}

// ---------------------------------------------------------------------------
extern "C" void kernel_launch(void* const* d_in, const int* in_sizes, int n_in,
                              void* d_out, int out_size)
{
    const float* x  = (const float*)d_in[0];
    const float* Wq = (const float*)d_in[1];
    const float* bq = (const float*)d_in[2];
    const float* Wk = (const float*)d_in[3];
    const float* bk = (const float*)d_in[4];
    const float* Wv = (const float*)d_in[5];
    const float* bv = (const float*)d_in[6];
    float* out = (float*)d_out;

    __half *xh, *wh, *qh, *kh, *vt, *ph;
    float *rs, *bb;
    cudaGetSymbolAddress((void**)&xh, g_x);
    cudaGetSymbolAddress((void**)&wh, g_w);
    cudaGetSymbolAddress((void**)&qh, g_q);
    cudaGetSymbolAddress((void**)&kh, g_k);
    cudaGetSymbolAddress((void**)&vt, g_vt);
    cudaGetSymbolAddress((void**)&ph, g_p);
    cudaGetSymbolAddress((void**)&rs, g_rs);
    cudaGetSymbolAddress((void**)&bb, g_b);

    cudaFuncSetAttribute(mega_kernel, cudaFuncAttributeMaxDynamicSharedMemorySize, SMEM_GB);

    // launch 1: prep (x, bias, W) + zero scheduling counters
    prep_all_kernel<<<NB_X + 12 + NB_W + 1, 256>>>(x, xh, bq, bk, bv, bb,
                                                   Wq, Wk, Wv, wh);

    // launch 2: persistent fused QKV -> scores(+exp+sums) -> PV(normalized)
    mega_kernel<<<NCTA_PERSIST, 128, SMEM_GB>>>(xh, wh, bb, qh, kh, vt,
                                                ph, rs, out);
}

// round 15
// speedup vs baseline: 1.1294x; 1.1294x over previous
#include <cuda_runtime.h>
#include <cuda_fp16.h>
#include <cstdint>

// ---------------------------------------------------------------------------
// SelfAttention: out = softmax((xWq+bq)(xWk+bk)^T / 32) (xWv+bv)
// B=4, N=2048, D=1024, fp32 in/out.  fp16 mma.sync m16n8k16 (fp32 accum).
// ldmatrix.m8n8.x4 (natural B) and .x4.trans (B kept [K,N]-natural: W for
// QKV, V for PV) -> no W transpose prep, no V scatter, no Vt buffer.
// Softmax fused away (unnormalized exp + distributed rowsums).
// 128-thread CTAs, 64x64 warp tiles, BK=64, 3-stage cp.async.
// PV GEMM sits at the ncu capture slot (my launch #4).
// ---------------------------------------------------------------------------

static constexpr int  BATCH = 4;
static constexpr int  SEQ   = 2048;
static constexpr int  DIM   = 1024;
static constexpr long MROWS = (long)BATCH * SEQ;   // 8192
static constexpr int  NCTA_N = SEQ / 128;          // 16 score col-tiles per row

// Scratch (__device__ globals: allocation-free rule)
__device__ __half g_x[MROWS * DIM];
__device__ __half g_w[(long)DIM * 3 * DIM];        // W concat [1024 k][3072 n]
__device__ __half g_q[MROWS * DIM];
__device__ __half g_k[MROWS * DIM];
__device__ __half g_v[MROWS * DIM];                // V natural [token][dim]
__device__ __half g_p[(long)BATCH * SEQ * SEQ];    // unnormalized exp, fp16
__device__ float  g_rs[MROWS * NCTA_N];            // per-row partial sums
__device__ float  g_b[3 * DIM];

// ---------------- helpers ----------------
__device__ __forceinline__ int swz(int r) {        // smem chunk swizzle (A path)
    return ((r & 3) << 1) | ((r >> 2) & 1);
}
__device__ __forceinline__ uint32_t smem_u32(const void* p) {
    uint32_t a;
    asm("{ .reg .u64 t; cvta.to.shared.u64 t, %1; cvt.u32.u64 %0, t; }" : "=r"(a) : "l"(p));
    return a;
}
__device__ __forceinline__ void cp16(uint32_t dst, const void* src) {
    asm volatile("cp.async.cg.shared.global [%0], [%1], 16;" :: "r"(dst), "l"(src));
}
__device__ __forceinline__ void cp_commit() { asm volatile("cp.async.commit_group;" ::: "memory"); }
template <int N>
__device__ __forceinline__ void cp_wait() { asm volatile("cp.async.wait_group %0;" :: "n"(N) : "memory"); }

__device__ __forceinline__ void ldsm4(uint32_t& r0, uint32_t& r1,
                                      uint32_t& r2, uint32_t& r3, uint32_t addr) {
    asm volatile("ldmatrix.sync.aligned.m8n8.x4.shared.b16 {%0,%1,%2,%3}, [%4];"
                 : "=r"(r0), "=r"(r1), "=r"(r2), "=r"(r3) : "r"(addr));
}
__device__ __forceinline__ void ldsm4t(uint32_t& r0, uint32_t& r1,
                                       uint32_t& r2, uint32_t& r3, uint32_t addr) {
    asm volatile("ldmatrix.sync.aligned.m8n8.x4.trans.shared.b16 {%0,%1,%2,%3}, [%4];"
                 : "=r"(r0), "=r"(r1), "=r"(r2), "=r"(r3) : "r"(addr));
}

__device__ __forceinline__ void mma_f16(float c[4],
                                        uint32_t a0, uint32_t a1, uint32_t a2, uint32_t a3,
                                        uint32_t b0, uint32_t b1) {
    asm volatile(
        "mma.sync.aligned.m16n8k16.row.col.f32.f16.f16.f32 "
        "{%0,%1,%2,%3}, {%4,%5,%6,%7}, {%8,%9}, {%0,%1,%2,%3};"
        : "+f"(c[0]), "+f"(c[1]), "+f"(c[2]), "+f"(c[3])
        : "r"(a0), "r"(a1), "r"(a2), "r"(a3), "r"(b0), "r"(b1));
}

// ---------------------------------------------------------------------------
// GEMM: C = A[M,K] @ op(B), fp16 in, fp32 accum.  128x128 CTA tile,
// 128 threads (4 warps, 64x64 warp tiles), BK=64, 3-stage cp.async.
// TRB=0: B stored [N,K] (row = n, k-major)   -> natural ldmatrix.
// TRB=1: B stored [K,N] (row = k, n-major)   -> ldmatrix.trans, 256B rows,
//        swizzle cn ^= (row&15).
// MODE 0: PV: fp32 store scaled by 1/rowsum (rs via `bias` pointer).
// MODE 1: fused QKV: +bias -> half; col<1024 -> Q, <2048 -> K, else V
//         (all natural half2 stores).
// MODE 2: scores: e=exp(s/32) -> fp16 P (via Cq) + row partial sums (via Cf).
// ---------------------------------------------------------------------------
static constexpr int STAGES  = 3;
static constexpr int TILE_B  = 128 * 64 * 2;       // 16 KB per operand tile
static constexpr int STAGE_B = 2 * TILE_B;         // 32 KB
static constexpr int SMEM_GB = STAGES * STAGE_B;   // 98304 B

template <int MODE, int TRB>
__global__ void __launch_bounds__(128, 2) gemm_h(
    const __half* __restrict__ A, const __half* __restrict__ B,
    const float* __restrict__ bias, float* __restrict__ Cf,
    __half* __restrict__ Cq, __half* __restrict__ Ck, __half* __restrict__ Cv,
    int N, int K, int ldb, long sA, long sB, long sC)
{
    extern __shared__ uint32_t sm[];

    A  += (long)blockIdx.z * sA;
    B  += (long)blockIdx.z * sB;
    Cf += (long)blockIdx.z * sC;

    const int tid  = threadIdx.x;
    const int warp = tid >> 5, lane = tid & 31;
    const int g = lane >> 2, tg = lane & 3;
    const int wm = warp >> 1, wn = warp & 1;        // 2x2 warps, 64x64 tiles
    const int m0 = blockIdx.y * 128, n0 = blockIdx.x * 128;

    const __half* Ag = A + (long)m0 * K;
    const __half* Bg = TRB ? (B + n0) : (B + (long)n0 * ldb);

    const uint32_t sbase = smem_u32(sm);

    auto load_stage = [&](int kt, int s) {
        const uint32_t as_ = sbase + (uint32_t)(s * STAGE_B);
        const uint32_t bs_ = as_ + TILE_B;
        #pragma unroll
        for (int i = 0; i < 8; i++) {               // A: 128 rows x 8 chunks
            int lin = tid + i * 128;
            int r = lin >> 3, c = lin & 7;
            uint32_t off = (uint32_t)(r * 128 + ((c ^ swz(r)) << 4));
            cp16(as_ + off, Ag + (long)r * K + kt * 64 + c * 8);
        }
        #pragma unroll
        for (int i = 0; i < 8; i++) {
            int lin = tid + i * 128;
            if (TRB) {                              // B: 64 k-rows x 16 chunks
                int r = lin >> 4, c = lin & 15;
                uint32_t off = (uint32_t)(r * 256 + ((c ^ (r & 15)) << 4));
                cp16(bs_ + off, Bg + (long)(kt * 64 + r) * ldb + c * 8);
            } else {                                // B: 128 n-rows x 8 chunks
                int r = lin >> 3, c = lin & 7;
                uint32_t off = (uint32_t)(r * 128 + ((c ^ swz(r)) << 4));
                cp16(bs_ + off, Bg + (long)r * ldb + kt * 64 + c * 8);
            }
        }
    };

    float acc[4][8][4];
    #pragma unroll
    for (int i = 0; i < 4; i++)
        #pragma unroll
        for (int j = 0; j < 8; j++)
            #pragma unroll
            for (int l = 0; l < 4; l++) acc[i][j][l] = 0.f;

    const int nk = K / 64;

    #pragma unroll
    for (int s = 0; s < STAGES - 1; s++) { load_stage(s, s); cp_commit(); }

    // ldmatrix per-lane geometry
    const int sw    = swz(lane & 7);
    const int aRow  = (lane & 7) | (lane & 8);      // A frag rows
    const int aCbit = lane >> 4;
    const int bRow  = (lane & 7) | ((lane >> 1) & 8);   // TRB=0 path
    const int bCbit = (lane >> 3) & 1;
    const int trow  = (lane & 7) | (((lane >> 3) & 1) << 3);  // TRB=1: k-row 0..15
    const int tnc   = (lane >> 4) & 1;                        // TRB=1: n-chunk bit

    int scur = 0;
    for (int kt = 0; kt < nk; kt++) {
        cp_wait<STAGES - 2>();
        __syncthreads();

        int pf = kt + STAGES - 1;
        if (pf < nk) {
            int sp = scur + (STAGES - 1); if (sp >= STAGES) sp -= STAGES;
            load_stage(pf, sp);
        }
        cp_commit();

        const uint32_t asb = sbase + (uint32_t)(scur * STAGE_B);
        const uint32_t aB0 = asb + (uint32_t)((wm * 64 + aRow) * 128);
        const uint32_t bB  = asb + TILE_B +
            (TRB ? 0u : (uint32_t)((wn * 64 + bRow) * 128));

        #pragma unroll
        for (int kkb = 0; kkb < 4; kkb++) {
            const uint32_t aco = (uint32_t)(((2 * kkb + aCbit) ^ sw) << 4);

            uint32_t af[4][4];
            #pragma unroll
            for (int mt = 0; mt < 4; mt++)
                ldsm4(af[mt][0], af[mt][1], af[mt][2], af[mt][3],
                      aB0 + (uint32_t)(mt * 16 * 128) + aco);

            uint32_t bf[16];
            if (TRB) {
                const uint32_t rb = (uint32_t)((kkb * 16 + trow) * 256);
                #pragma unroll
                for (int p = 0; p < 4; p++) {
                    int cn = wn * 8 + p * 2 + tnc;
                    ldsm4t(bf[4 * p], bf[4 * p + 1], bf[4 * p + 2], bf[4 * p + 3],
                           bB + rb + (uint32_t)(((cn ^ trow) & 15) << 4));
                }
            } else {
                const uint32_t bco = (uint32_t)(((2 * kkb + bCbit) ^ sw) << 4);
                #pragma unroll
                for (int p = 0; p < 4; p++)
                    ldsm4(bf[4 * p], bf[4 * p + 1], bf[4 * p + 2], bf[4 * p + 3],
                          bB + (uint32_t)(p * 2048) + bco);
            }

            #pragma unroll
            for (int mt = 0; mt < 4; mt++)
                #pragma unroll
                for (int nt = 0; nt < 8; nt++) {
                    int bi = ((nt >> 1) << 2) | ((nt & 1) << 1);
                    mma_f16(acc[mt][nt],
                            af[mt][0], af[mt][1], af[mt][2], af[mt][3],
                            bf[bi], bf[bi + 1]);
                }
        }
        if (++scur == STAGES) scur = 0;
    }

    if (MODE == 2) {
        // ------- scores epilogue: exp, fp16 P, per-row partial sums -------
        __syncthreads();                            // reuse stage smem
        float* rsm = (float*)sm;                    // [128 rows][2 halves]
        const float SC = 0.03125f;
        #pragma unroll
        for (int mt = 0; mt < 4; mt++) {
            int rr = wm * 64 + mt * 16 + g;
            int r0 = m0 + rr;
            float s0 = 0.f, s1 = 0.f;
            #pragma unroll
            for (int nt = 0; nt < 8; nt++) {
                int cc = n0 + wn * 64 + nt * 8 + tg * 2;
                __half2 h0 = __floats2half2_rn(__expf(acc[mt][nt][0] * SC),
                                               __expf(acc[mt][nt][1] * SC));
                __half2 h1 = __floats2half2_rn(__expf(acc[mt][nt][2] * SC),
                                               __expf(acc[mt][nt][3] * SC));
                long prow = (long)blockIdx.z * SEQ;
                *(__half2*)(Cq + (prow + r0) * SEQ + cc)     = h0;
                *(__half2*)(Cq + (prow + r0 + 8) * SEQ + cc) = h1;
                s0 += __half2float(h0.x) + __half2float(h0.y);
                s1 += __half2float(h1.x) + __half2float(h1.y);
            }
            #pragma unroll
            for (int o = 1; o < 4; o <<= 1) {
                s0 += __shfl_xor_sync(0xffffffffu, s0, o);
                s1 += __shfl_xor_sync(0xffffffffu, s1, o);
            }
            if (tg == 0) {
                rsm[(rr)     * 2 + wn] = s0;
                rsm[(rr + 8) * 2 + wn] = s1;
            }
        }
        __syncthreads();
        if (tid < 128) {
            float sum = rsm[tid * 2] + rsm[tid * 2 + 1];
            Cf[((long)blockIdx.z * SEQ + m0 + tid) * NCTA_N + blockIdx.x] = sum;
        }
        return;
    }

    // epilogue (MODE 0 / 1)
    #pragma unroll
    for (int mt = 0; mt < 4; mt++) {
        int r0 = m0 + wm * 64 + mt * 16 + g;
        float inv0 = 1.f, inv1 = 1.f;
        if (MODE == 0) {
            const float4* rs0 = (const float4*)(bias +
                ((long)blockIdx.z * SEQ + r0) * NCTA_N) + tg;
            const float4* rs1 = (const float4*)(bias +
                ((long)blockIdx.z * SEQ + r0 + 8) * NCTA_N) + tg;
            float4 a4 = *rs0, b4 = *rs1;
            float t0 = a4.x + a4.y + a4.z + a4.w;
            float t1 = b4.x + b4.y + b4.z + b4.w;
            #pragma unroll
            for (int o = 1; o < 4; o <<= 1) {
                t0 += __shfl_xor_sync(0xffffffffu, t0, o);
                t1 += __shfl_xor_sync(0xffffffffu, t1, o);
            }
            inv0 = 1.f / t0; inv1 = 1.f / t1;
        }
        #pragma unroll
        for (int nt = 0; nt < 8; nt++) {
            int cc = n0 + wn * 64 + nt * 8 + tg * 2;
            float v0 = acc[mt][nt][0], v1 = acc[mt][nt][1];
            float v2 = acc[mt][nt][2], v3 = acc[mt][nt][3];
            if (MODE == 1) {
                float b0 = bias[cc], b1 = bias[cc + 1];
                v0 += b0; v1 += b1; v2 += b0; v3 += b1;
                int buf = cc >> 10, loc = cc & 1023;
                __half* dst = buf == 0 ? Cq : (buf == 1 ? Ck : Cv);
                *(__half2*)(dst + (long)r0 * DIM + loc) =
                    __floats2half2_rn(v0, v1);
                *(__half2*)(dst + (long)(r0 + 8) * DIM + loc) =
                    __floats2half2_rn(v2, v3);
            } else {                                 // MODE 0: normalized fp32
                *(float2*)(Cf + (long)r0 * N + cc) =
                    make_float2(v0 * inv0, v1 * inv0);
                *(float2*)(Cf + (long)(r0 + 8) * N + cc) =
                    make_float2(v2 * inv1, v3 * inv1);
            }
        }
    }
}

// ---------------------------------------------------------------------------
// merged prep: x -> fp16, bias concat, W -> fp16 concat [k][3072] (no transp)
// ---------------------------------------------------------------------------
static constexpr int NB_X = (int)(MROWS * DIM / 4 / 256);   // 8192 blocks
static constexpr int NB_W = 3 * (DIM * DIM / 4 / 256);      // 3072 blocks

__global__ void __launch_bounds__(256) prep_all_kernel(
    const float* __restrict__ in, __half* __restrict__ out,
    const float* __restrict__ b0, const float* __restrict__ b1,
    const float* __restrict__ b2, float* __restrict__ bcat,
    const float* __restrict__ W0, const float* __restrict__ W1,
    const float* __restrict__ W2, __half* __restrict__ wout)
{
    const int bx = blockIdx.x;
    if (bx < NB_X) {
        int i = bx * 256 + threadIdx.x;
        float4 v = ((const float4*)in)[i];
        ((__half2*)out)[2 * i]     = __floats2half2_rn(v.x, v.y);
        ((__half2*)out)[2 * i + 1] = __floats2half2_rn(v.z, v.w);
    } else if (bx < NB_X + 12) {
        int i = (bx - NB_X) * 256 + threadIdx.x;
        if (i < DIM)          bcat[i] = b0[i];
        else if (i < 2 * DIM) bcat[i] = b1[i - DIM];
        else                  bcat[i] = b2[i - 2 * DIM];
    } else {
        int widx = bx - NB_X - 12;                  // 1024 blocks per matrix
        int z    = widx >> 10;
        int rem  = widx & 1023;
        const float* W = z == 0 ? W0 : (z == 1 ? W1 : W2);
        int e = (rem * 256 + threadIdx.x) * 4;      // element in matrix z
        int k = e >> 10, n = e & 1023;
        float4 v = *(const float4*)(W + e);
        __half2* d = (__half2*)(wout + (long)k * (3 * DIM) + z * DIM + n);
        d[0] = __floats2half2_rn(v.x, v.y);
        d[1] = __floats2half2_rn(v.z, v.w);
    }
}

// ---------------------------------------------------------------------------
extern "C" void kernel_launch(void* const* d_in, const int* in_sizes, int n_in,
                              void* d_out, int out_size)
{
    const float* x  = (const float*)d_in[0];
    const float* Wq = (const float*)d_in[1];
    const float* bq = (const float*)d_in[2];
    const float* Wk = (const float*)d_in[3];
    const float* bk = (const float*)d_in[4];
    const float* Wv = (const float*)d_in[5];
    const float* bv = (const float*)d_in[6];
    float* out = (float*)d_out;

    __half *xh, *wh, *qh, *kh, *vh, *ph;
    float *rs, *bb;
    cudaGetSymbolAddress((void**)&xh, g_x);
    cudaGetSymbolAddress((void**)&wh, g_w);
    cudaGetSymbolAddress((void**)&qh, g_q);
    cudaGetSymbolAddress((void**)&kh, g_k);
    cudaGetSymbolAddress((void**)&vh, g_v);
    cudaGetSymbolAddress((void**)&ph, g_p);
    cudaGetSymbolAddress((void**)&rs, g_rs);
    cudaGetSymbolAddress((void**)&bb, g_b);

    cudaFuncSetAttribute(gemm_h<1, 1>, cudaFuncAttributeMaxDynamicSharedMemorySize, SMEM_GB);
    cudaFuncSetAttribute(gemm_h<2, 0>, cudaFuncAttributeMaxDynamicSharedMemorySize, SMEM_GB);
    cudaFuncSetAttribute(gemm_h<0, 1>, cudaFuncAttributeMaxDynamicSharedMemorySize, SMEM_GB);

    // launch 1: merged prep (x, bias, W convert — no transpose)
    prep_all_kernel<<<NB_X + 12 + NB_W, 256>>>(x, xh, bq, bk, bv, bb,
                                               Wq, Wk, Wv, wh);

    // launch 2: fused QKV [8192,3072], B = W natural [k][3072] (trans path)
    const dim3 gp(3 * DIM / 128, (int)(MROWS / 128), 1);   // 24 x 64
    gemm_h<1, 1><<<gp, 128, SMEM_GB>>>(xh, wh, bb, nullptr, qh, kh, vh,
                                       3 * DIM, DIM, 3 * DIM, 0, 0, 0);

    // launch 3: scores + exp + partial sums (B = K natural [n][k])
    const dim3 gs(SEQ / 128, SEQ / 128, BATCH);
    gemm_h<2, 0><<<gs, 128, SMEM_GB>>>(qh, kh, nullptr, rs, ph, nullptr, nullptr,
                                       SEQ, DIM, DIM,
                                       (long)SEQ * DIM, (long)SEQ * DIM, 0);

    // launch 4 (ncu capture slot): PV, B = V natural [token][dim] (trans path)
    const dim3 go(DIM / 128, SEQ / 128, BATCH);
    gemm_h<0, 1><<<go, 128, SMEM_GB>>>(ph, vh, rs, out, nullptr, nullptr, nullptr,
                                       DIM, SEQ, DIM,
                                       (long)SEQ * SEQ, (long)SEQ * DIM, (long)SEQ * DIM);
}

// round 16
// speedup vs baseline: 1.1368x; 1.0066x over previous
#include <cuda_runtime.h>
#include <cuda_fp16.h>
#include <cstdint>

// ---------------------------------------------------------------------------
// SelfAttention: out = softmax((xWq+bq)(xWk+bk)^T / 32) (xWv+bv)
// B=4, N=2048, D=1024, fp32 in/out.  fp16 mma.sync m16n8k16 (fp32 accum).
// ldmatrix.m8n8.x4 fragment loads (natural), 128-thread CTAs, 64x64 warp
// tiles, BK=64, 3-stage cp.async.  Softmax fused away (unnormalized exp +
// distributed rowsums).  QKV fused; V tiles (uniform per CTA) transpose
// through smem -> coalesced Vt stores.  QKV at ncu capture slot (#4).
// ---------------------------------------------------------------------------

static constexpr int  BATCH = 4;
static constexpr int  SEQ   = 2048;
static constexpr int  DIM   = 1024;
static constexpr long MROWS = (long)BATCH * SEQ;   // 8192
static constexpr int  NCTA_N = SEQ / 128;          // 16 score col-tiles per row

// Scratch (__device__ globals: allocation-free rule)
__device__ __half g_x[MROWS * DIM];
__device__ __half g_w[(long)3 * DIM * DIM];        // W^T concat [3072 n][1024 k]
__device__ __half g_q[MROWS * DIM];
__device__ __half g_k[MROWS * DIM];
__device__ __half g_vt[(long)BATCH * DIM * SEQ];   // V^T per batch [dim][token]
__device__ __half g_p[(long)BATCH * SEQ * SEQ];    // unnormalized exp, fp16
__device__ float  g_rs[MROWS * NCTA_N];            // per-row partial sums
__device__ float  g_b[3 * DIM];

// ---------------- helpers ----------------
__device__ __forceinline__ int swz(int r) {        // smem chunk swizzle
    return ((r & 3) << 1) | ((r >> 2) & 1);
}
__device__ __forceinline__ uint32_t smem_u32(const void* p) {
    uint32_t a;
    asm("{ .reg .u64 t; cvta.to.shared.u64 t, %1; cvt.u32.u64 %0, t; }" : "=r"(a) : "l"(p));
    return a;
}
__device__ __forceinline__ void cp16(uint32_t dst, const void* src) {
    asm volatile("cp.async.cg.shared.global [%0], [%1], 16;" :: "r"(dst), "l"(src));
}
__device__ __forceinline__ void cp_commit() { asm volatile("cp.async.commit_group;" ::: "memory"); }
template <int N>
__device__ __forceinline__ void cp_wait() { asm volatile("cp.async.wait_group %0;" :: "n"(N) : "memory"); }

__device__ __forceinline__ void ldsm4(uint32_t& r0, uint32_t& r1,
                                      uint32_t& r2, uint32_t& r3, uint32_t addr) {
    asm volatile("ldmatrix.sync.aligned.m8n8.x4.shared.b16 {%0,%1,%2,%3}, [%4];"
                 : "=r"(r0), "=r"(r1), "=r"(r2), "=r"(r3) : "r"(addr));
}

__device__ __forceinline__ void mma_f16(float c[4],
                                        uint32_t a0, uint32_t a1, uint32_t a2, uint32_t a3,
                                        uint32_t b0, uint32_t b1) {
    asm volatile(
        "mma.sync.aligned.m16n8k16.row.col.f32.f16.f16.f32 "
        "{%0,%1,%2,%3}, {%4,%5,%6,%7}, {%8,%9}, {%0,%1,%2,%3};"
        : "+f"(c[0]), "+f"(c[1]), "+f"(c[2]), "+f"(c[3])
        : "r"(a0), "r"(a1), "r"(a2), "r"(a3), "r"(b0), "r"(b1));
}

// ---------------------------------------------------------------------------
// GEMM: C = A[M,K] @ B[N,K]^T, fp16 in, fp32 accum.  128x128 CTA tile,
// 128 threads (4 warps, 64x64 warp tiles), BK=64, 3-stage cp.async, ldmatrix.
// MODE 0: PV: fp32 store scaled by 1/rowsum (rs via `bias` pointer).
// MODE 1: fused QKV: +bias -> half; CTA uniform per output: n0<1024 -> Q,
//         <2048 -> K (half2 stores); else V -> smem-transpose -> coalesced Vt.
// MODE 2: scores: e=exp(s/32) -> fp16 P (via Cq) + row partial sums (via Cf).
// ---------------------------------------------------------------------------
static constexpr int STAGES  = 3;
static constexpr int TILE_B  = 128 * 64 * 2;       // 16 KB per operand tile
static constexpr int STAGE_B = 2 * TILE_B;         // 32 KB
static constexpr int SMEM_GB = STAGES * STAGE_B;   // 98304 B

template <int MODE>
__global__ void __launch_bounds__(128, 2) gemm_h(
    const __half* __restrict__ A, const __half* __restrict__ B,
    const float* __restrict__ bias, float* __restrict__ Cf,
    __half* __restrict__ Cq, __half* __restrict__ Ck, __half* __restrict__ Cv,
    int N, int K, int ldb, long sA, long sB, long sC)
{
    extern __shared__ uint32_t sm[];

    A  += (long)blockIdx.z * sA;
    B  += (long)blockIdx.z * sB;
    Cf += (long)blockIdx.z * sC;

    const int tid  = threadIdx.x;
    const int warp = tid >> 5, lane = tid & 31;
    const int g = lane >> 2, tg = lane & 3;
    const int wm = warp >> 1, wn = warp & 1;        // 2x2 warps, 64x64 tiles
    const int m0 = blockIdx.y * 128, n0 = blockIdx.x * 128;

    const __half* Ag = A + (long)m0 * K;
    const __half* Bg = B + (long)n0 * ldb;

    const uint32_t sbase = smem_u32(sm);

    auto load_stage = [&](int kt, int s) {
        const uint32_t as_ = sbase + (uint32_t)(s * STAGE_B);
        const uint32_t bs_ = as_ + TILE_B;
        #pragma unroll
        for (int i = 0; i < 8; i++) {               // A: 128 rows x 8 chunks
            int lin = tid + i * 128;
            int r = lin >> 3, c = lin & 7;
            uint32_t off = (uint32_t)(r * 128 + ((c ^ swz(r)) << 4));
            cp16(as_ + off, Ag + (long)r * K + kt * 64 + c * 8);
        }
        #pragma unroll
        for (int i = 0; i < 8; i++) {               // B: same geometry
            int lin = tid + i * 128;
            int r = lin >> 3, c = lin & 7;
            uint32_t off = (uint32_t)(r * 128 + ((c ^ swz(r)) << 4));
            cp16(bs_ + off, Bg + (long)r * ldb + kt * 64 + c * 8);
        }
    };

    float acc[4][8][4];
    #pragma unroll
    for (int i = 0; i < 4; i++)
        #pragma unroll
        for (int j = 0; j < 8; j++)
            #pragma unroll
            for (int l = 0; l < 4; l++) acc[i][j][l] = 0.f;

    const int nk = K / 64;

    #pragma unroll
    for (int s = 0; s < STAGES - 1; s++) { load_stage(s, s); cp_commit(); }

    // ldmatrix per-lane geometry (frag rows satisfy row&7 == lane&7)
    const int sw    = swz(lane & 7);
    const int aRow  = (lane & 7) | (lane & 8);
    const int aCbit = lane >> 4;
    const int bRow  = (lane & 7) | ((lane >> 1) & 8);
    const int bCbit = (lane >> 3) & 1;

    int scur = 0;
    for (int kt = 0; kt < nk; kt++) {
        cp_wait<STAGES - 2>();
        __syncthreads();

        int pf = kt + STAGES - 1;
        if (pf < nk) {
            int sp = scur + (STAGES - 1); if (sp >= STAGES) sp -= STAGES;
            load_stage(pf, sp);
        }
        cp_commit();

        const uint32_t asb = sbase + (uint32_t)(scur * STAGE_B);
        const uint32_t aB0 = asb + (uint32_t)((wm * 64 + aRow) * 128);
        const uint32_t bB  = asb + TILE_B + (uint32_t)((wn * 64 + bRow) * 128);

        #pragma unroll
        for (int kkb = 0; kkb < 4; kkb++) {
            const uint32_t aco = (uint32_t)(((2 * kkb + aCbit) ^ sw) << 4);
            const uint32_t bco = (uint32_t)(((2 * kkb + bCbit) ^ sw) << 4);

            uint32_t af[4][4];
            #pragma unroll
            for (int mt = 0; mt < 4; mt++)
                ldsm4(af[mt][0], af[mt][1], af[mt][2], af[mt][3],
                      aB0 + (uint32_t)(mt * 16 * 128) + aco);

            uint32_t bf[16];
            #pragma unroll
            for (int p = 0; p < 4; p++)
                ldsm4(bf[4 * p], bf[4 * p + 1], bf[4 * p + 2], bf[4 * p + 3],
                      bB + (uint32_t)(p * 2048) + bco);

            #pragma unroll
            for (int mt = 0; mt < 4; mt++)
                #pragma unroll
                for (int nt = 0; nt < 8; nt++) {
                    int bi = ((nt >> 1) << 2) | ((nt & 1) << 1);
                    mma_f16(acc[mt][nt],
                            af[mt][0], af[mt][1], af[mt][2], af[mt][3],
                            bf[bi], bf[bi + 1]);
                }
        }
        if (++scur == STAGES) scur = 0;
    }

    if (MODE == 2) {
        // ------- scores epilogue: exp, fp16 P, per-row partial sums -------
        __syncthreads();                            // reuse stage smem
        float* rsm = (float*)sm;                    // [128 rows][2 halves]
        const float SC = 0.03125f;
        #pragma unroll
        for (int mt = 0; mt < 4; mt++) {
            int rr = wm * 64 + mt * 16 + g;
            int r0 = m0 + rr;
            float s0 = 0.f, s1 = 0.f;
            #pragma unroll
            for (int nt = 0; nt < 8; nt++) {
                int cc = n0 + wn * 64 + nt * 8 + tg * 2;
                __half2 h0 = __floats2half2_rn(__expf(acc[mt][nt][0] * SC),
                                               __expf(acc[mt][nt][1] * SC));
                __half2 h1 = __floats2half2_rn(__expf(acc[mt][nt][2] * SC),
                                               __expf(acc[mt][nt][3] * SC));
                long prow = (long)blockIdx.z * SEQ;
                *(__half2*)(Cq + (prow + r0) * SEQ + cc)     = h0;
                *(__half2*)(Cq + (prow + r0 + 8) * SEQ + cc) = h1;
                s0 += __half2float(h0.x) + __half2float(h0.y);
                s1 += __half2float(h1.x) + __half2float(h1.y);
            }
            #pragma unroll
            for (int o = 1; o < 4; o <<= 1) {
                s0 += __shfl_xor_sync(0xffffffffu, s0, o);
                s1 += __shfl_xor_sync(0xffffffffu, s1, o);
            }
            if (tg == 0) {
                rsm[(rr)     * 2 + wn] = s0;
                rsm[(rr + 8) * 2 + wn] = s1;
            }
        }
        __syncthreads();
        if (tid < 128) {
            float sum = rsm[tid * 2] + rsm[tid * 2 + 1];
            Cf[((long)blockIdx.z * SEQ + m0 + tid) * NCTA_N + blockIdx.x] = sum;
        }
        return;
    }

    if (MODE == 1 && n0 >= 2 * DIM) {
        // ---- V tile: +bias, transpose through smem, coalesced Vt stores ----
        __syncthreads();                            // stage smem free now
        __half* T = (__half*)sm;                    // [128 dim][136 tok] halves
        const int TS = 136;
        #pragma unroll
        for (int mt = 0; mt < 4; mt++) {
            int rl = wm * 64 + mt * 16 + g;         // token-local
            #pragma unroll
            for (int nt = 0; nt < 8; nt++) {
                int cc = n0 + wn * 64 + nt * 8 + tg * 2;
                int cl = cc & 127;                  // dim-local
                float b0 = bias[cc], b1 = bias[cc + 1];
                T[cl * TS + rl]           = __float2half_rn(acc[mt][nt][0] + b0);
                T[(cl + 1) * TS + rl]     = __float2half_rn(acc[mt][nt][1] + b1);
                T[cl * TS + rl + 8]       = __float2half_rn(acc[mt][nt][2] + b0);
                T[(cl + 1) * TS + rl + 8] = __float2half_rn(acc[mt][nt][3] + b1);
            }
        }
        __syncthreads();
        const int bb_ = m0 >> 11, tok0 = m0 & 2047;
        const int dim0 = n0 - 2 * DIM;
        #pragma unroll
        for (int p = 0; p < 4; p++) {
            int row = p * 32 + (tid >> 2), seg = tid & 3;     // 4 lanes/row
            const uint4* src = (const uint4*)(T + row * TS + seg * 32);
            uint4* dst = (uint4*)(Cv + ((long)bb_ * DIM + dim0 + row) * SEQ
                                  + tok0 + seg * 32);
            #pragma unroll
            for (int j = 0; j < 4; j++) dst[j] = src[j];
        }
        return;
    }

    // epilogue (MODE 0, or MODE 1 Q/K)
    #pragma unroll
    for (int mt = 0; mt < 4; mt++) {
        int r0 = m0 + wm * 64 + mt * 16 + g;
        float inv0 = 1.f, inv1 = 1.f;
        if (MODE == 0) {
            const float4* rs0 = (const float4*)(bias +
                ((long)blockIdx.z * SEQ + r0) * NCTA_N) + tg;
            const float4* rs1 = (const float4*)(bias +
                ((long)blockIdx.z * SEQ + r0 + 8) * NCTA_N) + tg;
            float4 a4 = *rs0, b4 = *rs1;
            float t0 = a4.x + a4.y + a4.z + a4.w;
            float t1 = b4.x + b4.y + b4.z + b4.w;
            #pragma unroll
            for (int o = 1; o < 4; o <<= 1) {
                t0 += __shfl_xor_sync(0xffffffffu, t0, o);
                t1 += __shfl_xor_sync(0xffffffffu, t1, o);
            }
            inv0 = 1.f / t0; inv1 = 1.f / t1;
        }
        #pragma unroll
        for (int nt = 0; nt < 8; nt++) {
            int cc = n0 + wn * 64 + nt * 8 + tg * 2;
            float v0 = acc[mt][nt][0], v1 = acc[mt][nt][1];
            float v2 = acc[mt][nt][2], v3 = acc[mt][nt][3];
            if (MODE == 1) {                         // Q or K (uniform per CTA)
                float b0 = bias[cc], b1 = bias[cc + 1];
                v0 += b0; v1 += b1; v2 += b0; v3 += b1;
                int loc = cc & 1023;
                __half* dst = (n0 < DIM) ? Cq : Ck;
                *(__half2*)(dst + (long)r0 * DIM + loc) =
                    __floats2half2_rn(v0, v1);
                *(__half2*)(dst + (long)(r0 + 8) * DIM + loc) =
                    __floats2half2_rn(v2, v3);
            } else {                                 // MODE 0: normalized fp32
                *(float2*)(Cf + (long)r0 * N + cc) =
                    make_float2(v0 * inv0, v1 * inv0);
                *(float2*)(Cf + (long)(r0 + 8) * N + cc) =
                    make_float2(v2 * inv1, v3 * inv1);
            }
        }
    }
}

// ---------------------------------------------------------------------------
// prep kernels (split in 3 so QKV lands at ncu capture slot #4)
// ---------------------------------------------------------------------------
static constexpr int NB_X = (int)(MROWS * DIM / 4 / 256);   // 8192 blocks

__global__ void __launch_bounds__(256) prep_x_kernel(
    const float* __restrict__ in, __half* __restrict__ out)
{
    int i = blockIdx.x * 256 + threadIdx.x;
    float4 v = ((const float4*)in)[i];
    ((__half2*)out)[2 * i]     = __floats2half2_rn(v.x, v.y);
    ((__half2*)out)[2 * i + 1] = __floats2half2_rn(v.z, v.w);
}

// all three W[k][n] -> wh[n][k] fp16 (concat), grid.z selects the matrix
__global__ void __launch_bounds__(256) prep_w_kernel(
    const float* __restrict__ W0, const float* __restrict__ W1,
    const float* __restrict__ W2, __half* __restrict__ out)
{
    __shared__ float t[32][33];
    const float* in = blockIdx.z == 0 ? W0 : (blockIdx.z == 1 ? W1 : W2);
    __half* dst = out + (long)blockIdx.z * DIM * DIM;
    int r0 = blockIdx.y * 32, c0 = blockIdx.x * 32;
    int tx = threadIdx.x & 31, ty = threadIdx.x >> 5;
    #pragma unroll
    for (int j = 0; j < 4; j++)
        t[ty + j * 8][tx] = in[(long)(r0 + ty + j * 8) * DIM + c0 + tx];
    __syncthreads();
    #pragma unroll
    for (int j = 0; j < 4; j++) {
        float v = t[tx][ty + j * 8];
        dst[(long)(c0 + ty + j * 8) * DIM + r0 + tx] = __float2half_rn(v);
    }
}

__global__ void __launch_bounds__(256) prep_b_kernel(
    const float* __restrict__ b0, const float* __restrict__ b1,
    const float* __restrict__ b2, float* __restrict__ bcat)
{
    int i = blockIdx.x * 256 + threadIdx.x;
    if (i < DIM)          bcat[i] = b0[i];
    else if (i < 2 * DIM) bcat[i] = b1[i - DIM];
    else                  bcat[i] = b2[i - 2 * DIM];
}

// ---------------------------------------------------------------------------
extern "C" void kernel_launch(void* const* d_in, const int* in_sizes, int n_in,
                              void* d_out, int out_size)
{
    const float* x  = (const float*)d_in[0];
    const float* Wq = (const float*)d_in[1];
    const float* bq = (const float*)d_in[2];
    const float* Wk = (const float*)d_in[3];
    const float* bk = (const float*)d_in[4];
    const float* Wv = (const float*)d_in[5];
    const float* bv = (const float*)d_in[6];
    float* out = (float*)d_out;

    __half *xh, *wh, *qh, *kh, *vt, *ph;
    float *rs, *bb;
    cudaGetSymbolAddress((void**)&xh, g_x);
    cudaGetSymbolAddress((void**)&wh, g_w);
    cudaGetSymbolAddress((void**)&qh, g_q);
    cudaGetSymbolAddress((void**)&kh, g_k);
    cudaGetSymbolAddress((void**)&vt, g_vt);
    cudaGetSymbolAddress((void**)&ph, g_p);
    cudaGetSymbolAddress((void**)&rs, g_rs);
    cudaGetSymbolAddress((void**)&bb, g_b);

    cudaFuncSetAttribute(gemm_h<0>, cudaFuncAttributeMaxDynamicSharedMemorySize, SMEM_GB);
    cudaFuncSetAttribute(gemm_h<1>, cudaFuncAttributeMaxDynamicSharedMemorySize, SMEM_GB);
    cudaFuncSetAttribute(gemm_h<2>, cudaFuncAttributeMaxDynamicSharedMemorySize, SMEM_GB);

    // launches 1-3: prep (x; W transposes; bias concat)
    prep_x_kernel<<<NB_X, 256>>>(x, xh);
    const dim3 tgw(DIM / 32, DIM / 32, 3);
    prep_w_kernel<<<tgw, 256>>>(Wq, Wk, Wv, wh);
    prep_b_kernel<<<12, 256>>>(bq, bk, bv, bb);

    // launch 4 (ncu capture slot): fused QKV [8192,3072]; V -> Vt coalesced
    const dim3 gp(3 * DIM / 128, (int)(MROWS / 128), 1);   // 24 x 64
    gemm_h<1><<<gp, 128, SMEM_GB>>>(xh, wh, bb, nullptr, qh, kh, vt,
                                    3 * DIM, DIM, DIM, 0, 0, 0);

    // launch 5: scores + exp + partial sums (P via Cq; sums via Cf=rs)
    const dim3 gs(SEQ / 128, SEQ / 128, BATCH);
    gemm_h<2><<<gs, 128, SMEM_GB>>>(qh, kh, nullptr, rs, ph, nullptr, nullptr,
                                    SEQ, DIM, DIM,
                                    (long)SEQ * DIM, (long)SEQ * DIM, 0);

    // launch 6: PV with rowsum normalization (rs via bias)
    const dim3 go(DIM / 128, SEQ / 128, BATCH);
    gemm_h<0><<<go, 128, SMEM_GB>>>(ph, vt, rs, out, nullptr, nullptr, nullptr,
                                    DIM, SEQ, SEQ,
                                    (long)SEQ * SEQ, (long)DIM * SEQ, (long)SEQ * DIM);
}